// round 9
// baseline (speedup 1.0000x reference)
#include <cuda_runtime.h>
#include <cuda_bf16.h>

#define NN   50
#define NN2  2500          // N*N
#define ATT  4000          // alpha steps / t-range
#define BB   512           // batch
#define PP   32            // features p
#define NP   (BB * PP)     // 16384 (b,p) pairs
#define CAP  32            // per-t slot capacity (P(overflow) ~ 1e-18)

// Scratch (static __device__ globals: allocation-free rule)
__device__ float g_F[NN2];                   // F = g @ w^2
__device__ float g_fT[(size_t)ATT * NN2];    // fT[t][j][i] (i fastest, 50-wide)
__device__ int   g_cnt[ATT];                 // per-t pair count (ticket counter)
__device__ int   g_slot[ATT * CAP];          // pair indices per t
__device__ float g_xT[(size_t)BB * PP * NN]; // xT[b][p][i] (i contiguous)

// ---------------------------------------------------------------------------
// Kernel A (grid 625 x 256): FOUR rows per block; w^2 staged in smem once and
// amortized over 4 row-streams. Each unrolled column-group issues 4
// independent g LDG.128s (separate accumulators), so the g stream keeps
// high MLP. Folds in Z init + g_cnt zero only (transpose moved to kB).
// ---------------------------------------------------------------------------
__global__ void kA_F(const float* __restrict__ g, const float* __restrict__ w,
                     float* __restrict__ outF,
                     const int* __restrict__ y_i, const float* __restrict__ mus,
                     float* __restrict__ Z) {
    int tid = threadIdx.x;
    int gid = blockIdx.x * 256 + tid;   // 160000 threads

    if (gid < BB * NN) {
        int b = gid / NN, i = gid - b * NN;
        Z[gid] = (float)PP * mus[(size_t)y_i[b] * NN + i];
    } else if (gid < BB * NN + ATT) {
        g_cnt[gid - BB * NN] = 0;
    }

    __shared__ float4 w2s[640];          // 625 used (10 KB)
    __shared__ float  red[4][8];

    const float4* w4 = (const float4*)w;
    for (int c = tid; c < NN2 / 4; c += 256) {
        float4 wv = w4[c];
        w2s[c] = make_float4(wv.x * wv.x, wv.y * wv.y, wv.z * wv.z, wv.w * wv.w);
    }
    __syncthreads();

    int row0 = blockIdx.x * 4;
    const float4* gr0 = (const float4*)(g + (size_t)(row0 + 0) * NN2);
    const float4* gr1 = (const float4*)(g + (size_t)(row0 + 1) * NN2);
    const float4* gr2 = (const float4*)(g + (size_t)(row0 + 2) * NN2);
    const float4* gr3 = (const float4*)(g + (size_t)(row0 + 3) * NN2);

    float s0 = 0.f, s1 = 0.f, s2 = 0.f, s3 = 0.f;
    #pragma unroll
    for (int cg = 0; cg < 3; cg++) {
        int c = tid + cg * 256;
        if (c < NN2 / 4) {
            float4 wv = w2s[c];
            float4 a = gr0[c];
            float4 b = gr1[c];
            float4 d = gr2[c];
            float4 e = gr3[c];
            s0 += a.x * wv.x + a.y * wv.y + a.z * wv.z + a.w * wv.w;
            s1 += b.x * wv.x + b.y * wv.y + b.z * wv.z + b.w * wv.w;
            s2 += d.x * wv.x + d.y * wv.y + d.z * wv.z + d.w * wv.w;
            s3 += e.x * wv.x + e.y * wv.y + e.z * wv.z + e.w * wv.w;
        }
    }

    #pragma unroll
    for (int o = 16; o; o >>= 1) {
        s0 += __shfl_down_sync(0xffffffffu, s0, o);
        s1 += __shfl_down_sync(0xffffffffu, s1, o);
        s2 += __shfl_down_sync(0xffffffffu, s2, o);
        s3 += __shfl_down_sync(0xffffffffu, s3, o);
    }
    int lane = tid & 31, wid = tid >> 5;
    if (lane == 0) {
        red[0][wid] = s0; red[1][wid] = s1; red[2][wid] = s2; red[3][wid] = s3;
    }
    __syncthreads();
    if (tid < 32) {
        int r = tid >> 3, wx = tid & 7;
        float v = red[r][wx];
        v += __shfl_down_sync(0xffffffffu, v, 4, 8);
        v += __shfl_down_sync(0xffffffffu, v, 2, 8);
        v += __shfl_down_sync(0xffffffffu, v, 1, 8);
        if (wx == 0) { g_F[row0 + r] = v; outF[row0 + r] = v; }
    }
}

// ---------------------------------------------------------------------------
// Kernel B (grid 1000 x 256): softmax table, 4 t per block, 64 threads per t.
// Folds in: hist+scatter (ticket = atomicAdd doubles as slot index) and the
// coalesced x->xT transpose (blocks < 512; this kernel is MUFU/store-bound,
// so the extra 6.6 MB of traffic rides free).
// ---------------------------------------------------------------------------
__global__ void kB_softmaxT(const float* __restrict__ alphas,
                            const int* __restrict__ x_i,
                            const float* __restrict__ x) {
    int gid = blockIdx.x * 256 + threadIdx.x;
    if (gid < NP) {
        int t = x_i[gid];
        int ticket = atomicAdd(&g_cnt[t], 1);
        if (ticket < CAP) g_slot[t * CAP + ticket] = gid;
    }

    __shared__ float Fs[NN2];
    __shared__ float tile[NN * PP];
    for (int idx = threadIdx.x; idx < NN2; idx += 256)
        Fs[idx] = g_F[idx];
    if (blockIdx.x < BB) {
        const float* src = x + (size_t)blockIdx.x * (NN * PP);
        for (int o = threadIdx.x; o < NN * PP; o += 256)
            tile[o] = src[o];                       // coalesced (p fastest)
    }
    __syncthreads();
    if (blockIdx.x < BB) {
        float* dst = g_xT + (size_t)blockIdx.x * (PP * NN);
        for (int o = threadIdx.x; o < PP * NN; o += 256) {
            int p = o / NN, i = o - p * NN;
            dst[o] = tile[i * PP + p];              // coalesced writes
        }
    }

    int lt = threadIdx.x >> 6;        // 0..3
    int i  = threadIdx.x & 63;        // row index
    int t  = (blockIdx.x << 2) + lt;
    if (i >= NN) return;

    float a = alphas[t];
    float e[NN];
    float s = 0.f;
    #pragma unroll
    for (int j = 0; j < NN; j++) {
        float v = __expf(-a * Fs[i * NN + j]);
        e[j] = v;
        s += v;
    }
    float rinv = __fdividef(1.0f, s);
    float* dst = g_fT + (size_t)t * NN2 + i;
    #pragma unroll
    for (int j = 0; j < NN; j++)
        dst[j * NN] = e[j] * rinv;
}

// ---------------------------------------------------------------------------
// Kernel C2 (grid 4000 x 64): one block per t. Loads fT[t] row into registers
// ONCE (thread i holds f[i][0..49]) and applies it to all pairs with this t,
// 4 pairs per pass from smem. Table traffic: 40MB instead of 164MB.
// ---------------------------------------------------------------------------
__global__ void kC2(const float* __restrict__ mus, float* __restrict__ Z) {
    int t = blockIdx.x;
    int cnt = g_cnt[t];
    if (cnt == 0) return;
    if (cnt > CAP) cnt = CAP;

    int i = threadIdx.x;              // 0..63, active < 50
    __shared__ float a_s[4][NN + 2];

    float freg[NN];
    float mu_i = 0.f;
    if (i < NN) {
        mu_i = mus[(size_t)t * NN + i];
        const float* fr = g_fT + (size_t)t * NN2 + i;
        #pragma unroll
        for (int j = 0; j < NN; j++) freg[j] = fr[j * NN];
    }

    for (int base = 0; base < cnt; base += 4) {
        if (i < NN) {
            #pragma unroll
            for (int k = 0; k < 4; k++) {
                int q = base + k;
                int pr = (q < cnt) ? g_slot[t * CAP + q] : 0;
                a_s[k][i] = g_xT[(size_t)pr * NN + i] - mu_i;
            }
        }
        __syncthreads();
        if (i < NN) {
            float acc0 = 0.f, acc1 = 0.f, acc2 = 0.f, acc3 = 0.f;
            #pragma unroll
            for (int j = 0; j < NN; j++) {
                float f = freg[j];
                acc0 += f * a_s[0][j];
                acc1 += f * a_s[1][j];
                acc2 += f * a_s[2][j];
                acc3 += f * a_s[3][j];
            }
            float acc[4] = {acc0, acc1, acc2, acc3};
            #pragma unroll
            for (int k = 0; k < 4; k++) {
                int q = base + k;
                if (q < cnt) {
                    int pr = g_slot[t * CAP + q];
                    int b = pr >> 5;
                    atomicAdd(&Z[b * NN + i], acc[k]);
                }
            }
        }
        __syncthreads();
    }
}

// ---------------------------------------------------------------------------
extern "C" void kernel_launch(void* const* d_in, const int* in_sizes, int n_in,
                              void* d_out, int out_size) {
    const float* x      = (const float*)d_in[0];   // [512,50,32]
    const int*   x_i    = (const int*)  d_in[1];   // [512,32]
    const int*   y_i    = (const int*)  d_in[2];   // [512]
    const float* g      = (const float*)d_in[3];   // [2500,2500]
    const float* w      = (const float*)d_in[4];   // [2500,1]
    const float* mus    = (const float*)d_in[5];   // [4000,50]
    const float* alphas = (const float*)d_in[6];   // [4000,1]

    float* Z    = (float*)d_out;        // [512*50]
    float* outF = Z + BB * NN;          // [2500]

    kA_F<<<625, 256>>>(g, w, outF, y_i, mus, Z);
    kB_softmaxT<<<ATT / 4, 256>>>(alphas, x_i, x);
    kC2<<<ATT, 64>>>(mus, Z);
}

// round 10
// speedup vs baseline: 1.4638x; 1.4638x over previous
#include <cuda_runtime.h>
#include <cuda_bf16.h>

#define NN   50
#define NN2  2500          // N*N
#define ATT  4000          // alpha steps / t-range
#define BB   512           // batch
#define PP   32            // features p
#define NP   (BB * PP)     // 16384 (b,p) pairs
#define CAP  32            // per-t slot capacity (P(overflow) ~ 1e-18)

// Scratch (static __device__ globals: allocation-free rule)
__device__ float g_F[NN2];                   // F = g @ w^2
__device__ float g_fT[(size_t)ATT * NN2];    // fT[t][j][i] (i fastest, 50-wide)
__device__ int   g_cnt[ATT];                 // per-t pair count (ticket counter)
__device__ int   g_slot[ATT * CAP];          // pair indices per t
__device__ float g_xT[(size_t)BB * PP * NN]; // xT[b][p][i] (i contiguous)

// ---------------------------------------------------------------------------
// Kernel A (grid 625 x 256): FOUR rows per block; w^2 staged in smem once and
// amortized over 4 row-streams (4 independent LDG.128 per column group keeps
// the g stream at high MLP). Folds in: Z init, g_cnt zero, and the coalesced
// smem-tile x->xT transpose (blocks < 512). kA has register headroom; kB does
// NOT (e[50] live across exp loop), so all folds live here.
// ---------------------------------------------------------------------------
__global__ void kA_F(const float* __restrict__ g, const float* __restrict__ w,
                     float* __restrict__ outF,
                     const int* __restrict__ y_i, const float* __restrict__ mus,
                     const float* __restrict__ x, float* __restrict__ Z) {
    int tid = threadIdx.x;
    int gid = blockIdx.x * 256 + tid;   // 160000 threads

    if (gid < BB * NN) {
        int b = gid / NN, i = gid - b * NN;
        Z[gid] = (float)PP * mus[(size_t)y_i[b] * NN + i];
    } else if (gid < BB * NN + ATT) {
        g_cnt[gid - BB * NN] = 0;
    }

    __shared__ float4 w2s[640];          // 625 used (10 KB)
    __shared__ float  tile[NN * PP];     // 6.4 KB
    __shared__ float  red[4][8];

    // Stage w^2 (coalesced float4; L2-resident after first wave)
    const float4* w4 = (const float4*)w;
    for (int c = tid; c < NN2 / 4; c += 256) {
        float4 wv = w4[c];
        w2s[c] = make_float4(wv.x * wv.x, wv.y * wv.y, wv.z * wv.z, wv.w * wv.w);
    }

    // Transpose read phase: block b (<512) loads x[b][50][32] coalesced
    if (blockIdx.x < BB) {
        const float* src = x + (size_t)blockIdx.x * (NN * PP);
        for (int o = tid; o < NN * PP; o += 256)
            tile[o] = src[o];
    }
    __syncthreads();

    // Transpose write phase: coalesced writes of xT[b][32][50]
    if (blockIdx.x < BB) {
        float* dst = g_xT + (size_t)blockIdx.x * (PP * NN);
        for (int o = tid; o < PP * NN; o += 256) {
            int p = o / NN, i = o - p * NN;
            dst[o] = tile[i * PP + p];
        }
    }

    // Matvec: rows 4*blockIdx .. +3; 625 float4 per row
    int row0 = blockIdx.x * 4;
    const float4* gr0 = (const float4*)(g + (size_t)(row0 + 0) * NN2);
    const float4* gr1 = (const float4*)(g + (size_t)(row0 + 1) * NN2);
    const float4* gr2 = (const float4*)(g + (size_t)(row0 + 2) * NN2);
    const float4* gr3 = (const float4*)(g + (size_t)(row0 + 3) * NN2);

    float s0 = 0.f, s1 = 0.f, s2 = 0.f, s3 = 0.f;
    #pragma unroll
    for (int cg = 0; cg < 3; cg++) {
        int c = tid + cg * 256;
        if (c < NN2 / 4) {
            float4 wv = w2s[c];
            float4 a = gr0[c];
            float4 b = gr1[c];
            float4 d = gr2[c];
            float4 e = gr3[c];
            s0 += a.x * wv.x + a.y * wv.y + a.z * wv.z + a.w * wv.w;
            s1 += b.x * wv.x + b.y * wv.y + b.z * wv.z + b.w * wv.w;
            s2 += d.x * wv.x + d.y * wv.y + d.z * wv.z + d.w * wv.w;
            s3 += e.x * wv.x + e.y * wv.y + e.z * wv.z + e.w * wv.w;
        }
    }

    #pragma unroll
    for (int o = 16; o; o >>= 1) {
        s0 += __shfl_down_sync(0xffffffffu, s0, o);
        s1 += __shfl_down_sync(0xffffffffu, s1, o);
        s2 += __shfl_down_sync(0xffffffffu, s2, o);
        s3 += __shfl_down_sync(0xffffffffu, s3, o);
    }
    int lane = tid & 31, wid = tid >> 5;
    if (lane == 0) {
        red[0][wid] = s0; red[1][wid] = s1; red[2][wid] = s2; red[3][wid] = s3;
    }
    __syncthreads();
    if (tid < 32) {
        int r = tid >> 3, wx = tid & 7;
        float v = red[r][wx];
        v += __shfl_down_sync(0xffffffffu, v, 4, 8);
        v += __shfl_down_sync(0xffffffffu, v, 2, 8);
        v += __shfl_down_sync(0xffffffffu, v, 1, 8);
        if (wx == 0) { g_F[row0 + r] = v; outF[row0 + r] = v; }
    }
}

// ---------------------------------------------------------------------------
// Kernel B (grid 1000 x 256): softmax table, 4 t per block, 64 threads per t.
// Folds in hist+scatter ONLY (ticket = atomicAdd doubles as slot index).
// Keep this kernel lean: e[50] lives across the exp loop; extra folds spill.
// ---------------------------------------------------------------------------
__global__ void kB_softmaxT(const float* __restrict__ alphas,
                            const int* __restrict__ x_i) {
    int gid = blockIdx.x * 256 + threadIdx.x;
    if (gid < NP) {
        int t = x_i[gid];
        int ticket = atomicAdd(&g_cnt[t], 1);
        if (ticket < CAP) g_slot[t * CAP + ticket] = gid;
    }

    __shared__ float Fs[NN2];
    for (int idx = threadIdx.x; idx < NN2; idx += 256)
        Fs[idx] = g_F[idx];
    __syncthreads();

    int lt = threadIdx.x >> 6;        // 0..3
    int i  = threadIdx.x & 63;        // row index
    int t  = (blockIdx.x << 2) + lt;
    if (i >= NN) return;

    float a = alphas[t];
    float e[NN];
    float s = 0.f;
    #pragma unroll
    for (int j = 0; j < NN; j++) {
        float v = __expf(-a * Fs[i * NN + j]);
        e[j] = v;
        s += v;
    }
    float rinv = __fdividef(1.0f, s);
    float* dst = g_fT + (size_t)t * NN2 + i;
    #pragma unroll
    for (int j = 0; j < NN; j++)
        dst[j * NN] = e[j] * rinv;
}

// ---------------------------------------------------------------------------
// Kernel C2 (grid 4000 x 64): one block per t. Loads fT[t] row into registers
// ONCE (thread i holds f[i][0..49]) and applies it to all pairs with this t,
// 4 pairs per pass from smem. Table traffic: 40MB instead of 164MB.
// ---------------------------------------------------------------------------
__global__ void kC2(const float* __restrict__ mus, float* __restrict__ Z) {
    int t = blockIdx.x;
    int cnt = g_cnt[t];
    if (cnt == 0) return;
    if (cnt > CAP) cnt = CAP;

    int i = threadIdx.x;              // 0..63, active < 50
    __shared__ float a_s[4][NN + 2];

    float freg[NN];
    float mu_i = 0.f;
    if (i < NN) {
        mu_i = mus[(size_t)t * NN + i];
        const float* fr = g_fT + (size_t)t * NN2 + i;
        #pragma unroll
        for (int j = 0; j < NN; j++) freg[j] = fr[j * NN];
    }

    for (int base = 0; base < cnt; base += 4) {
        if (i < NN) {
            #pragma unroll
            for (int k = 0; k < 4; k++) {
                int q = base + k;
                int pr = (q < cnt) ? g_slot[t * CAP + q] : 0;
                a_s[k][i] = g_xT[(size_t)pr * NN + i] - mu_i;
            }
        }
        __syncthreads();
        if (i < NN) {
            float acc0 = 0.f, acc1 = 0.f, acc2 = 0.f, acc3 = 0.f;
            #pragma unroll
            for (int j = 0; j < NN; j++) {
                float f = freg[j];
                acc0 += f * a_s[0][j];
                acc1 += f * a_s[1][j];
                acc2 += f * a_s[2][j];
                acc3 += f * a_s[3][j];
            }
            float acc[4] = {acc0, acc1, acc2, acc3};
            #pragma unroll
            for (int k = 0; k < 4; k++) {
                int q = base + k;
                if (q < cnt) {
                    int pr = g_slot[t * CAP + q];
                    int b = pr >> 5;
                    atomicAdd(&Z[b * NN + i], acc[k]);
                }
            }
        }
        __syncthreads();
    }
}

// ---------------------------------------------------------------------------
extern "C" void kernel_launch(void* const* d_in, const int* in_sizes, int n_in,
                              void* d_out, int out_size) {
    const float* x      = (const float*)d_in[0];   // [512,50,32]
    const int*   x_i    = (const int*)  d_in[1];   // [512,32]
    const int*   y_i    = (const int*)  d_in[2];   // [512]
    const float* g      = (const float*)d_in[3];   // [2500,2500]
    const float* w      = (const float*)d_in[4];   // [2500,1]
    const float* mus    = (const float*)d_in[5];   // [4000,50]
    const float* alphas = (const float*)d_in[6];   // [4000,1]

    float* Z    = (float*)d_out;        // [512*50]
    float* outF = Z + BB * NN;          // [2500]

    kA_F<<<625, 256>>>(g, w, outF, y_i, mus, x, Z);
    kB_softmaxT<<<ATT / 4, 256>>>(alphas, x_i);
    kC2<<<ATT, 64>>>(mus, Z);
}